// round 16
// baseline (speedup 1.0000x reference)
#include <cuda_runtime.h>
#include <cstdint>
#include <cstddef>

// Problem constants
#define NN 50000
#define EE 500000
#define PSTRIDE 1088
#define P2OFF   544

__device__ float g_p[(size_t)NN * PSTRIDE]; // precomputed node @ [W_top | W_mid]
__device__ float g_m[NN * 64];   // segment-sum of m_ij
__device__ float g_w[NN];        // segment-sum of coord_w
__device__ float g_r[NN * 3];    // segment-sum of rel_coords
__device__ int   g_is64;         // edge_index dtype flag

__device__ __forceinline__ float silu_f(float v) {
    return __fdividef(v, 1.0f + __expf(-v));
}

typedef unsigned long long u64t;

__device__ __forceinline__ void ffma2(u64t& d, u64t a, u64t b) {
    asm("fma.rn.f32x2 %0, %1, %2, %3;" : "=l"(d) : "l"(a), "l"(b), "l"(d));
}
__device__ __forceinline__ u64t pack2s(float v) {
    u64t r;
    unsigned int u = __float_as_uint(v);
    asm("mov.b64 %0, {%1, %2};" : "=l"(r) : "r"(u), "r"(u));
    return r;
}
__device__ __forceinline__ float2 unpack2(u64t v) {
    unsigned int lo, hi;
    asm("mov.b64 {%0, %1}, %2;" : "=r"(lo), "=r"(hi) : "l"(v));
    return make_float2(__uint_as_float(lo), __uint_as_float(hi));
}

// ---------------------------------------------------------------------------
// Detect edge_index dtype with one warp (int64 => all odd 32-bit words zero)
// ---------------------------------------------------------------------------
__global__ void detect_kernel(const int* __restrict__ ei32) {
    if (blockIdx.x == 0 && threadIdx.x < 32) {
        int lane = threadIdx.x;
        int nz = 0;
        #pragma unroll
        for (int r = 0; r < 2; r++) {
            int i = r * 32 + lane;
            if (ei32[2 * i + 1] != 0) nz = 1;
        }
        unsigned int any = __ballot_sync(0xffffffffu, nz);
        if (lane == 0) g_is64 = (any == 0u) ? 1 : 0;
    }
}

__global__ void zero_kernel() {
    int stride = gridDim.x * blockDim.x;
    int i = blockIdx.x * blockDim.x + threadIdx.x;
    for (int k = i; k < NN * 64; k += stride) g_m[k] = 0.0f;
    for (int k = i; k < NN; k += stride) g_w[k] = 0.0f;
    for (int k = i; k < NN * 3; k += stride) g_r[k] = 0.0f;
}

// ---------------------------------------------------------------------------
// Precompute kernel (R11 version)
// ---------------------------------------------------------------------------
#define PRE_SMEM_BYTES 100352

__global__ __launch_bounds__(256)
void pre_kernel(const float* __restrict__ x, const float* __restrict__ We1)
{
    extern __shared__ float sm[];
    float* s_x = sm;           // [128][132]
    float* s_w = sm + 16896;   // [128][64]

    const int tid  = threadIdx.x;
    const int lane = tid & 31;
    const int wrp  = tid >> 5;
    const int b0   = blockIdx.x * 128;

    for (int i = wrp; i < 128; i += 8) {
        int g = b0 + i;
        if (g < NN) {
            const float* xr = x + (size_t)g * 131;
            #pragma unroll
            for (int c = lane; c < 128; c += 32) s_x[i * 132 + c] = xr[c];
        } else {
            for (int c = lane; c < 128; c += 32) s_x[i * 132 + c] = 0.0f;
        }
    }
    __syncthreads();

    const int tx = tid & 15;
    const int ty = tid >> 4;

    for (int chunk = 0; chunk < 17; chunk++) {
        int cw0 = chunk * 64;
        for (int idx = tid; idx < 8192; idx += 256) {
            int k = idx >> 6, j = idx & 63;
            int c = cw0 + j;
            float v = 0.0f;
            if (c < 514)                     v = We1[k * 514 + c];
            else if (c >= P2OFF && c < 1058) v = We1[(128 + k) * 514 + (c - P2OFF)];
            s_w[idx] = v;
        }
        __syncthreads();

        u64t accp[8][2];
        #pragma unroll
        for (int i = 0; i < 8; i++) { accp[i][0] = 0ull; accp[i][1] = 0ull; }

        for (int k = 0; k < 128; k += 4) {
            float4 a[8];
            #pragma unroll
            for (int i = 0; i < 8; i++)
                a[i] = *(const float4*)&s_x[(ty * 8 + i) * 132 + k];
            #pragma unroll
            for (int kk = 0; kk < 4; kk++) {
                ulonglong2 B = *(const ulonglong2*)&s_w[(k + kk) * 64 + (tx << 2)];
                #pragma unroll
                for (int i = 0; i < 8; i++) {
                    float av = (kk == 0) ? a[i].x : (kk == 1) ? a[i].y : (kk == 2) ? a[i].z : a[i].w;
                    u64t Ap = pack2s(av);
                    ffma2(accp[i][0], Ap, B.x);
                    ffma2(accp[i][1], Ap, B.y);
                }
            }
        }
        #pragma unroll
        for (int i = 0; i < 8; i++) {
            int g = b0 + ty * 8 + i;
            if (g < NN) {
                float2 v0 = unpack2(accp[i][0]);
                float2 v1 = unpack2(accp[i][1]);
                float4 v = make_float4(v0.x, v0.y, v1.x, v1.y);
                *(float4*)&g_p[(size_t)g * PSTRIDE + cw0 + (tx << 2)] = v;
            }
        }
        __syncthreads();
    }
}

// ---------------------------------------------------------------------------
// Edge kernel (R9/R11 proven version: pipelined gather + SMEM-staged GEMM2)
// 128 edges/block, 256 threads. SMEM = 70912 bytes.
// ---------------------------------------------------------------------------
#define EDGE_SMEM_BYTES 70912

__global__ __launch_bounds__(256, 2)
void edge_kernel(const float* __restrict__ x,
                 const void* __restrict__ ei_raw,
                 const float* __restrict__ We1, const float* __restrict__ be1,
                 const float* __restrict__ We2, const float* __restrict__ be2,
                 const float* __restrict__ Wc1, const float* __restrict__ bc1,
                 const float* __restrict__ Wc2, const float* __restrict__ bc2)
{
    extern __shared__ float sm[];
    float* s_h    = sm;                    // [32][132]
    float* s_w2   = sm + 4224;             // [32][64]
    float* s_m    = sm + 6272;             // [64][132]
    float* s_wc   = sm + 14720;            // [64][32]
    int*   s_dst  = (int*)(sm + 16768);
    int*   s_soff = (int*)(sm + 16896);
    float* s_dist = sm + 17024;
    float* s_rel  = sm + 17152;
    float* s_bb   = sm + 17536;
    float* s_wd   = sm + 17568;
    int*   s_doff = (int*)(sm + 17600);

    const int tid = threadIdx.x;
    const int is64 = g_is64;
    const long long* ei64 = (const long long*)ei_raw;
    const int*       ei32 = (const int*)ei_raw;

    if (tid < 128) {
        int e = tid;
        long long ge = (long long)blockIdx.x * 128 + e;
        int s = -1, d = -1;
        if (ge < EE) {
            if (is64) { s = (int)ei64[ge]; d = (int)ei64[EE + ge]; }
            else      { s = ei32[ge];      d = ei32[EE + ge]; }
            if (s < 0 || s >= NN || d < 0 || d >= NN) { s = -1; d = -1; }
        }
        float r0 = 0.0f, r1 = 0.0f, r2 = 0.0f, dist = 0.0f;
        if (d >= 0) {
            const float* xs = x + (size_t)s * 131;
            const float* xd = x + (size_t)d * 131;
            r0 = xs[128] - xd[128];
            r1 = xs[129] - xd[129];
            r2 = xs[130] - xd[130];
            dist = sqrtf(r0 * r0 + r1 * r1 + r2 * r2);
        }
        s_dst[e]  = d;
        s_doff[e] = (d >= 0) ? d * PSTRIDE : 0;
        s_soff[e] = (d >= 0) ? s * PSTRIDE + P2OFF : P2OFF;
        s_dist[e] = dist;
        s_rel[e * 3 + 0] = r0;
        s_rel[e * 3 + 1] = r1;
        s_rel[e * 3 + 2] = r2;
    }
    if (tid < 32) {
        s_bb[tid] = be1[tid];
        s_wd[tid] = We1[256 * 514 + tid];
    }
    __syncthreads();

    const int e_g = tid >> 1;
    const int qb  = tid & 1;
    const int dflag = s_dst[e_g];
    const int doff  = s_doff[e_g];
    const int soff  = s_soff[e_g];
    const float dist = s_dist[e_g];

    const int tx = tid & 15;
    const int ty = tid >> 4;
    const int e0 = ty * 8;

    u64t macc[4][4];
    #pragma unroll
    for (int p = 0; p < 4; p++)
        #pragma unroll
        for (int j = 0; j < 4; j++) macc[p][j] = 0ull;

    float4 P1[4], P2[4];
    #pragma unroll
    for (int it = 0; it < 4; it++) {
        int c = 4 * (qb + 2 * it);
        P1[it] = *(const float4*)&g_p[(size_t)(doff + c)];
        P2[it] = *(const float4*)&g_p[(size_t)(soff + c)];
    }
    float4 T1 = make_float4(0.f, 0.f, 0.f, 0.f);
    float4 T2 = make_float4(0.f, 0.f, 0.f, 0.f);

    for (int chunk = 0; chunk < 16; chunk++) {
        int c0 = chunk * 32;

        #pragma unroll
        for (int it = 0; it < 4; it++) {
            int q = qb + 2 * it;
            float4 wd4 = *(const float4*)&s_wd[4 * q];
            float4 bb4 = *(const float4*)&s_bb[4 * q];
            float h0 = silu_f(fmaf(dist, wd4.x, P1[it].x + P2[it].x + bb4.x));
            float h1 = silu_f(fmaf(dist, wd4.y, P1[it].y + P2[it].y + bb4.y));
            float h2 = silu_f(fmaf(dist, wd4.z, P1[it].z + P2[it].z + bb4.z));
            float h3 = silu_f(fmaf(dist, wd4.w, P1[it].w + P2[it].w + bb4.w));
            if (dflag < 0) { h0 = 0.f; h1 = 0.f; h2 = 0.f; h3 = 0.f; }
            s_h[(4 * q + 0) * 132 + e_g] = h0;
            s_h[(4 * q + 1) * 132 + e_g] = h1;
            s_h[(4 * q + 2) * 132 + e_g] = h2;
            s_h[(4 * q + 3) * 132 + e_g] = h3;
        }
        #pragma unroll
        for (int l = 0; l < 8; l++) {
            int idx = l * 256 + tid;
            int k = idx >> 6, j = idx & 63;
            s_w2[idx] = We2[(c0 + k) * 64 + j];
        }
        __syncthreads();

        if (chunk < 15) {
            int c0n = c0 + 32;
            #pragma unroll
            for (int it = 0; it < 4; it++) {
                int c = c0n + 4 * (qb + 2 * it);
                P1[it] = *(const float4*)&g_p[(size_t)(doff + c)];
                P2[it] = *(const float4*)&g_p[(size_t)(soff + c)];
            }
            if (tid < 32) {
                int col = c0n + tid;
                s_bb[tid] = be1[col];
                s_wd[tid] = We1[256 * 514 + col];
            }
        } else if (qb == 0) {
            T1 = *(const float4*)&g_p[(size_t)(doff + 512)];
            T2 = *(const float4*)&g_p[(size_t)(soff + 512)];
        }

        #pragma unroll 4
        for (int c = 0; c < 32; c++) {
            ulonglong2 A0 = *(const ulonglong2*)&s_h[c * 132 + e0];
            ulonglong2 A1 = *(const ulonglong2*)&s_h[c * 132 + e0 + 4];
            float4 bv = *(const float4*)&s_w2[c * 64 + (tx << 2)];
            u64t B0 = pack2s(bv.x), B1 = pack2s(bv.y), B2 = pack2s(bv.z), B3 = pack2s(bv.w);
            ffma2(macc[0][0], A0.x, B0); ffma2(macc[0][1], A0.x, B1);
            ffma2(macc[0][2], A0.x, B2); ffma2(macc[0][3], A0.x, B3);
            ffma2(macc[1][0], A0.y, B0); ffma2(macc[1][1], A0.y, B1);
            ffma2(macc[1][2], A0.y, B2); ffma2(macc[1][3], A0.y, B3);
            ffma2(macc[2][0], A1.x, B0); ffma2(macc[2][1], A1.x, B1);
            ffma2(macc[2][2], A1.x, B2); ffma2(macc[2][3], A1.x, B3);
            ffma2(macc[3][0], A1.y, B0); ffma2(macc[3][1], A1.y, B1);
            ffma2(macc[3][2], A1.y, B2); ffma2(macc[3][3], A1.y, B3);
        }
        __syncthreads();
    }

    // tail: cols 512, 513
    if (tid < 128)
        s_w2[tid] = We2[(512 + (tid >> 6)) * 64 + (tid & 63)];
    if (qb == 0) {
        float wd0 = We1[256 * 514 + 512], wd1 = We1[256 * 514 + 513];
        float b0 = be1[512], b1 = be1[513];
        float h0 = silu_f(fmaf(dist, wd0, T1.x + T2.x + b0));
        float h1 = silu_f(fmaf(dist, wd1, T1.y + T2.y + b1));
        if (dflag < 0) { h0 = 0.f; h1 = 0.f; }
        s_h[e_g]       = h0;
        s_h[132 + e_g] = h1;
    }
    __syncthreads();
    #pragma unroll
    for (int c = 0; c < 2; c++) {
        ulonglong2 A0 = *(const ulonglong2*)&s_h[c * 132 + e0];
        ulonglong2 A1 = *(const ulonglong2*)&s_h[c * 132 + e0 + 4];
        float4 bv = *(const float4*)&s_w2[c * 64 + (tx << 2)];
        u64t B0 = pack2s(bv.x), B1 = pack2s(bv.y), B2 = pack2s(bv.z), B3 = pack2s(bv.w);
        ffma2(macc[0][0], A0.x, B0); ffma2(macc[0][1], A0.x, B1);
        ffma2(macc[0][2], A0.x, B2); ffma2(macc[0][3], A0.x, B3);
        ffma2(macc[1][0], A0.y, B0); ffma2(macc[1][1], A0.y, B1);
        ffma2(macc[1][2], A0.y, B2); ffma2(macc[1][3], A0.y, B3);
        ffma2(macc[2][0], A1.x, B0); ffma2(macc[2][1], A1.x, B1);
        ffma2(macc[2][2], A1.x, B2); ffma2(macc[2][3], A1.x, B3);
        ffma2(macc[3][0], A1.y, B0); ffma2(macc[3][1], A1.y, B1);
        ffma2(macc[3][2], A1.y, B2); ffma2(macc[3][3], A1.y, B3);
    }
    __syncthreads();

    // m_ij = silu(m + b_e2); store + atomic scatter
    float mval[8][4];
    #pragma unroll
    for (int j = 0; j < 4; j++) {
        float b = be2[tx * 4 + j];
        #pragma unroll
        for (int p = 0; p < 4; p++) {
            float2 v = unpack2(macc[p][j]);
            mval[2 * p][j]     = silu_f(v.x + b);
            mval[2 * p + 1][j] = silu_f(v.y + b);
        }
    }
    #pragma unroll
    for (int j = 0; j < 4; j++)
        #pragma unroll
        for (int i = 0; i < 8; i++)
            s_m[(tx * 4 + j) * 132 + e0 + i] = mval[i][j];
    #pragma unroll
    for (int i = 0; i < 8; i++) {
        int d = s_dst[e0 + i];
        if (d >= 0) {
            #pragma unroll
            for (int j = 0; j < 4; j++)
                atomicAdd(&g_m[d * 64 + tx * 4 + j], mval[i][j]);
        }
    }
    __syncthreads();

    // GEMM3 (64->256) + silu + dot W_c2 (FFMA2)
    float cw[8];
    #pragma unroll
    for (int i = 0; i < 8; i++) cw[i] = 0.0f;

    for (int c0 = 0; c0 < 256; c0 += 32) {
        for (int idx = tid; idx < 2048; idx += 256) {
            int k = idx >> 5, j = idx & 31;
            s_wc[idx] = Wc1[k * 256 + c0 + j];
        }
        __syncthreads();

        u64t acc[4][2];
        #pragma unroll
        for (int p = 0; p < 4; p++) { acc[p][0] = 0ull; acc[p][1] = 0ull; }

        for (int k = 0; k < 64; k += 4) {
            #pragma unroll
            for (int kk = 0; kk < 4; kk++) {
                ulonglong2 A0 = *(const ulonglong2*)&s_m[(k + kk) * 132 + e0];
                ulonglong2 A1 = *(const ulonglong2*)&s_m[(k + kk) * 132 + e0 + 4];
                float2 bv = *(const float2*)&s_wc[(k + kk) * 32 + (tx << 1)];
                u64t B0 = pack2s(bv.x), B1 = pack2s(bv.y);
                ffma2(acc[0][0], A0.x, B0); ffma2(acc[0][1], A0.x, B1);
                ffma2(acc[1][0], A0.y, B0); ffma2(acc[1][1], A0.y, B1);
                ffma2(acc[2][0], A1.x, B0); ffma2(acc[2][1], A1.x, B1);
                ffma2(acc[3][0], A1.y, B0); ffma2(acc[3][1], A1.y, B1);
            }
        }
        float bb0 = bc1[c0 + tx * 2], bb1 = bc1[c0 + tx * 2 + 1];
        float w20 = Wc2[c0 + tx * 2], w21 = Wc2[c0 + tx * 2 + 1];
        #pragma unroll
        for (int p = 0; p < 4; p++) {
            float2 v0 = unpack2(acc[p][0]);
            float2 v1 = unpack2(acc[p][1]);
            cw[2 * p]     += silu_f(v0.x + bb0) * w20 + silu_f(v1.x + bb1) * w21;
            cw[2 * p + 1] += silu_f(v0.y + bb0) * w20 + silu_f(v1.y + bb1) * w21;
        }
        __syncthreads();
    }

    #pragma unroll
    for (int off = 8; off >= 1; off >>= 1)
        #pragma unroll
        for (int i = 0; i < 8; i++)
            cw[i] += __shfl_xor_sync(0xffffffffu, cw[i], off);

    if (tx == 0) {
        float bc2v = bc2[0];
        #pragma unroll
        for (int i = 0; i < 8; i++) {
            int d = s_dst[e0 + i];
            if (d >= 0) {
                atomicAdd(&g_w[d], cw[i] + bc2v);
                atomicAdd(&g_r[d * 3 + 0], s_rel[(e0 + i) * 3 + 0]);
                atomicAdd(&g_r[d * 3 + 1], s_rel[(e0 + i) * 3 + 1]);
                atomicAdd(&g_r[d * 3 + 2], s_rel[(e0 + i) * 3 + 2]);
            }
        }
    }
}

// ---------------------------------------------------------------------------
// Node kernel v2: 32 nodes/block, 256 threads, 3 blocks/SM.
// coords_out + fused MLP (192->256 silu ->128) + residual.
// Shared (floats): s_nin [32][196] (6272) | s_w1 [192][32] (6144)
//                  | s_h1 [32][36] (1152) | s_w2 [32][128] (4096) = 17664 fl
// ---------------------------------------------------------------------------
#define NODE_SMEM_BYTES 70656

__global__ __launch_bounds__(256, 3)
void node_kernel(const float* __restrict__ x,
                 const float* __restrict__ Wn1, const float* __restrict__ bn1,
                 const float* __restrict__ Wn2, const float* __restrict__ bn2,
                 float* __restrict__ out)
{
    extern __shared__ float sm[];
    float* s_nin = sm;              // [32][196]
    float* s_w1  = sm + 6272;       // [192][32]
    float* s_h1  = sm + 12416;      // [32 cols][36 nodes]
    float* s_w2  = sm + 13568;      // [32][128]

    const int tid  = threadIdx.x;
    const int lane = tid & 31;
    const int wrp  = tid >> 5;
    const int b0   = blockIdx.x * 32;

    for (int i = wrp; i < 32; i += 8) {
        int g = b0 + i;
        if (g < NN) {
            const float* xr = x + (size_t)g * 131;
            #pragma unroll
            for (int c = lane; c < 128; c += 32) s_nin[i * 196 + c] = xr[c];
            #pragma unroll
            for (int c = lane; c < 64; c += 32) s_nin[i * 196 + 128 + c] = g_m[g * 64 + c];
            if (lane < 4) s_nin[i * 196 + 192 + lane] = 0.0f;
            if (lane < 3)
                out[(size_t)g * 131 + 128 + lane] = xr[128 + lane] + g_w[g] * g_r[g * 3 + lane];
        } else {
            for (int c = lane; c < 196; c += 32) s_nin[i * 196 + c] = 0.0f;
        }
    }
    __syncthreads();

    const int tx = tid & 15;   // col-groups
    const int ty = tid >> 4;   // node-groups of 2

    u64t pacc[2][4];   // node i x col-pair q (GEMM2 output: 2 nodes x 8 cols)
    #pragma unroll
    for (int i = 0; i < 2; i++)
        #pragma unroll
        for (int q = 0; q < 4; q++) pacc[i][q] = 0ull;

    for (int c0 = 0; c0 < 256; c0 += 32) {
        for (int idx = tid; idx < 6144; idx += 256) {
            int k = idx >> 5, j = idx & 31;
            s_w1[idx] = Wn1[k * 256 + c0 + j];
        }
        __syncthreads();

        u64t acc1p[2];
        acc1p[0] = 0ull; acc1p[1] = 0ull;

        for (int k = 0; k < 192; k += 4) {
            float4 a0 = *(const float4*)&s_nin[(ty * 2 + 0) * 196 + k];
            float4 a1 = *(const float4*)&s_nin[(ty * 2 + 1) * 196 + k];
            #pragma unroll
            for (int kk = 0; kk < 4; kk++) {
                u64t bp = *(const u64t*)&s_w1[(k + kk) * 32 + (tx << 1)];
                float av0 = (kk == 0) ? a0.x : (kk == 1) ? a0.y : (kk == 2) ? a0.z : a0.w;
                float av1 = (kk == 0) ? a1.x : (kk == 1) ? a1.y : (kk == 2) ? a1.z : a1.w;
                ffma2(acc1p[0], pack2s(av0), bp);
                ffma2(acc1p[1], pack2s(av1), bp);
            }
        }
        __syncthreads();

        {
            float bjx = bn1[c0 + tx * 2];
            float bjy = bn1[c0 + tx * 2 + 1];
            #pragma unroll
            for (int i = 0; i < 2; i++) {
                float2 v = unpack2(acc1p[i]);
                s_h1[(tx * 2)     * 36 + ty * 2 + i] = silu_f(v.x + bjx);
                s_h1[(tx * 2 + 1) * 36 + ty * 2 + i] = silu_f(v.y + bjy);
            }
        }
        for (int idx = tid; idx < 4096; idx += 256) {
            int k = idx >> 7, j = idx & 127;
            s_w2[idx] = Wn2[(c0 + k) * 128 + j];
        }
        __syncthreads();

        #pragma unroll 4
        for (int c = 0; c < 32; c++) {
            float2 a = *(const float2*)&s_h1[c * 36 + ty * 2];
            ulonglong2 B0 = *(const ulonglong2*)&s_w2[c * 128 + tx * 8];
            ulonglong2 B1 = *(const ulonglong2*)&s_w2[c * 128 + tx * 8 + 4];
            u64t A0 = pack2s(a.x);
            u64t A1 = pack2s(a.y);
            ffma2(pacc[0][0], A0, B0.x);
            ffma2(pacc[0][1], A0, B0.y);
            ffma2(pacc[0][2], A0, B1.x);
            ffma2(pacc[0][3], A0, B1.y);
            ffma2(pacc[1][0], A1, B0.x);
            ffma2(pacc[1][1], A1, B0.y);
            ffma2(pacc[1][2], A1, B1.x);
            ffma2(pacc[1][3], A1, B1.y);
        }
        __syncthreads();
    }

    #pragma unroll
    for (int i = 0; i < 2; i++) {
        int g = b0 + ty * 2 + i;
        if (g < NN) {
            #pragma unroll
            for (int q = 0; q < 4; q++) {
                float2 v = unpack2(pacc[i][q]);
                int col = tx * 8 + 2 * q;
                out[(size_t)g * 131 + col] =
                    v.x + bn2[col] + s_nin[(ty * 2 + i) * 196 + col];
                out[(size_t)g * 131 + col + 1] =
                    v.y + bn2[col + 1] + s_nin[(ty * 2 + i) * 196 + col + 1];
            }
        }
    }
}

// ---------------------------------------------------------------------------
extern "C" void kernel_launch(void* const* d_in, const int* in_sizes, int n_in,
                              void* d_out, int out_size)
{
    const float* x   = (const float*)d_in[0];
    const void*  ei  = d_in[1];
    const float* We1 = (const float*)d_in[2];
    const float* be1 = (const float*)d_in[3];
    const float* We2 = (const float*)d_in[4];
    const float* be2 = (const float*)d_in[5];
    const float* Wc1 = (const float*)d_in[6];
    const float* bc1 = (const float*)d_in[7];
    const float* Wc2 = (const float*)d_in[8];
    const float* bc2 = (const float*)d_in[9];
    const float* Wn1 = (const float*)d_in[10];
    const float* bn1 = (const float*)d_in[11];
    const float* Wn2 = (const float*)d_in[12];
    const float* bn2 = (const float*)d_in[13];
    float* out = (float*)d_out;

    cudaFuncSetAttribute(pre_kernel,  cudaFuncAttributeMaxDynamicSharedMemorySize, PRE_SMEM_BYTES);
    cudaFuncSetAttribute(edge_kernel, cudaFuncAttributeMaxDynamicSharedMemorySize, EDGE_SMEM_BYTES);
    cudaFuncSetAttribute(node_kernel, cudaFuncAttributeMaxDynamicSharedMemorySize, NODE_SMEM_BYTES);

    detect_kernel<<<1, 32>>>((const int*)ei);
    zero_kernel<<<1024, 256>>>();
    pre_kernel<<<(NN + 127) / 128, 256, PRE_SMEM_BYTES>>>(x, We1);
    edge_kernel<<<(EE + 127) / 128, 256, EDGE_SMEM_BYTES>>>(
        x, ei, We1, be1, We2, be2, Wc1, bc1, Wc2, bc2);
    node_kernel<<<(NN + 31) / 32, 256, NODE_SMEM_BYTES>>>(
        x, Wn1, bn1, Wn2, bn2, out);
}

// round 17
// speedup vs baseline: 1.0680x; 1.0680x over previous
#include <cuda_runtime.h>
#include <cstdint>
#include <cstddef>

// Problem constants
#define NN 50000
#define EE 500000
#define PSTRIDE 1088
#define P2OFF   544

__device__ float g_p[(size_t)NN * PSTRIDE]; // precomputed node @ [W_top | W_mid]
__device__ float g_m[NN * 64];   // segment-sum of m_ij
__device__ float g_w[NN];        // segment-sum of coord_w
__device__ float g_r[NN * 3];    // segment-sum of rel_coords
__device__ int   g_is64;         // edge_index dtype flag

__device__ __forceinline__ float silu_f(float v) {
    return __fdividef(v, 1.0f + __expf(-v));
}

typedef unsigned long long u64t;

__device__ __forceinline__ void ffma2(u64t& d, u64t a, u64t b) {
    asm("fma.rn.f32x2 %0, %1, %2, %3;" : "=l"(d) : "l"(a), "l"(b), "l"(d));
}
__device__ __forceinline__ u64t pack2s(float v) {
    u64t r;
    unsigned int u = __float_as_uint(v);
    asm("mov.b64 %0, {%1, %2};" : "=l"(r) : "r"(u), "r"(u));
    return r;
}
__device__ __forceinline__ float2 unpack2(u64t v) {
    unsigned int lo, hi;
    asm("mov.b64 {%0, %1}, %2;" : "=r"(lo), "=r"(hi) : "l"(v));
    return make_float2(__uint_as_float(lo), __uint_as_float(hi));
}

// ---------------------------------------------------------------------------
// Zero accumulators + edge_index dtype detect (fused; runs every launch)
// ---------------------------------------------------------------------------
__global__ void zero_kernel(const int* __restrict__ ei32) {
    if (blockIdx.x == 0 && threadIdx.x < 32) {
        int lane = threadIdx.x;
        int nz = 0;
        #pragma unroll
        for (int r = 0; r < 2; r++) {
            int i = r * 32 + lane;
            if (ei32[2 * i + 1] != 0) nz = 1;
        }
        unsigned int any = __ballot_sync(0xffffffffu, nz);
        if (lane == 0) g_is64 = (any == 0u) ? 1 : 0;
    }
    int stride = gridDim.x * blockDim.x;
    int i = blockIdx.x * blockDim.x + threadIdx.x;
    for (int k = i; k < NN * 64; k += stride) g_m[k] = 0.0f;
    for (int k = i; k < NN; k += stride) g_w[k] = 0.0f;
    for (int k = i; k < NN * 3; k += stride) g_r[k] = 0.0f;
}

// ---------------------------------------------------------------------------
// Precompute kernel (R11 version, 128 nodes/block)
// ---------------------------------------------------------------------------
#define PRE_SMEM_BYTES 100352

__global__ __launch_bounds__(256)
void pre_kernel(const float* __restrict__ x, const float* __restrict__ We1)
{
    extern __shared__ float sm[];
    float* s_x = sm;           // [128][132]
    float* s_w = sm + 16896;   // [128][64]

    const int tid  = threadIdx.x;
    const int lane = tid & 31;
    const int wrp  = tid >> 5;
    const int b0   = blockIdx.x * 128;

    for (int i = wrp; i < 128; i += 8) {
        int g = b0 + i;
        if (g < NN) {
            const float* xr = x + (size_t)g * 131;
            #pragma unroll
            for (int c = lane; c < 128; c += 32) s_x[i * 132 + c] = xr[c];
        } else {
            for (int c = lane; c < 128; c += 32) s_x[i * 132 + c] = 0.0f;
        }
    }
    __syncthreads();

    const int tx = tid & 15;
    const int ty = tid >> 4;

    for (int chunk = 0; chunk < 17; chunk++) {
        int cw0 = chunk * 64;
        for (int idx = tid; idx < 8192; idx += 256) {
            int k = idx >> 6, j = idx & 63;
            int c = cw0 + j;
            float v = 0.0f;
            if (c < 514)                     v = We1[k * 514 + c];
            else if (c >= P2OFF && c < 1058) v = We1[(128 + k) * 514 + (c - P2OFF)];
            s_w[idx] = v;
        }
        __syncthreads();

        u64t accp[8][2];
        #pragma unroll
        for (int i = 0; i < 8; i++) { accp[i][0] = 0ull; accp[i][1] = 0ull; }

        for (int k = 0; k < 128; k += 4) {
            float4 a[8];
            #pragma unroll
            for (int i = 0; i < 8; i++)
                a[i] = *(const float4*)&s_x[(ty * 8 + i) * 132 + k];
            #pragma unroll
            for (int kk = 0; kk < 4; kk++) {
                ulonglong2 B = *(const ulonglong2*)&s_w[(k + kk) * 64 + (tx << 2)];
                #pragma unroll
                for (int i = 0; i < 8; i++) {
                    float av = (kk == 0) ? a[i].x : (kk == 1) ? a[i].y : (kk == 2) ? a[i].z : a[i].w;
                    u64t Ap = pack2s(av);
                    ffma2(accp[i][0], Ap, B.x);
                    ffma2(accp[i][1], Ap, B.y);
                }
            }
        }
        #pragma unroll
        for (int i = 0; i < 8; i++) {
            int g = b0 + ty * 8 + i;
            if (g < NN) {
                float2 v0 = unpack2(accp[i][0]);
                float2 v1 = unpack2(accp[i][1]);
                float4 v = make_float4(v0.x, v0.y, v1.x, v1.y);
                *(float4*)&g_p[(size_t)g * PSTRIDE + cw0 + (tx << 2)] = v;
            }
        }
        __syncthreads();
    }
}

// ---------------------------------------------------------------------------
// Edge kernel (R9 structure; staging vectorized to .128 ops)
// 128 edges/block, 256 threads. SMEM = 70912 bytes.
// ---------------------------------------------------------------------------
#define EDGE_SMEM_BYTES 70912

__global__ __launch_bounds__(256, 2)
void edge_kernel(const float* __restrict__ x,
                 const void* __restrict__ ei_raw,
                 const float* __restrict__ We1, const float* __restrict__ be1,
                 const float* __restrict__ We2, const float* __restrict__ be2,
                 const float* __restrict__ Wc1, const float* __restrict__ bc1,
                 const float* __restrict__ Wc2, const float* __restrict__ bc2)
{
    extern __shared__ float sm[];
    float* s_h    = sm;                    // [32][132]
    float* s_w2   = sm + 4224;             // [32][64]
    float* s_m    = sm + 6272;             // [64][132]
    float* s_wc   = sm + 14720;            // [64][32]
    int*   s_dst  = (int*)(sm + 16768);
    int*   s_soff = (int*)(sm + 16896);
    float* s_dist = sm + 17024;
    float* s_rel  = sm + 17152;
    float* s_bb   = sm + 17536;
    float* s_wd   = sm + 17568;
    int*   s_doff = (int*)(sm + 17600);

    const int tid = threadIdx.x;
    const int is64 = g_is64;
    const long long* ei64 = (const long long*)ei_raw;
    const int*       ei32 = (const int*)ei_raw;

    if (tid < 128) {
        int e = tid;
        long long ge = (long long)blockIdx.x * 128 + e;
        int s = -1, d = -1;
        if (ge < EE) {
            if (is64) { s = (int)ei64[ge]; d = (int)ei64[EE + ge]; }
            else      { s = ei32[ge];      d = ei32[EE + ge]; }
            if (s < 0 || s >= NN || d < 0 || d >= NN) { s = -1; d = -1; }
        }
        float r0 = 0.0f, r1 = 0.0f, r2 = 0.0f, dist = 0.0f;
        if (d >= 0) {
            const float* xs = x + (size_t)s * 131;
            const float* xd = x + (size_t)d * 131;
            r0 = xs[128] - xd[128];
            r1 = xs[129] - xd[129];
            r2 = xs[130] - xd[130];
            dist = sqrtf(r0 * r0 + r1 * r1 + r2 * r2);
        }
        s_dst[e]  = d;
        s_doff[e] = (d >= 0) ? d * PSTRIDE : 0;
        s_soff[e] = (d >= 0) ? s * PSTRIDE + P2OFF : P2OFF;
        s_dist[e] = dist;
        s_rel[e * 3 + 0] = r0;
        s_rel[e * 3 + 1] = r1;
        s_rel[e * 3 + 2] = r2;
    }
    if (tid < 32) {
        s_bb[tid] = be1[tid];
        s_wd[tid] = We1[256 * 514 + tid];
    }
    __syncthreads();

    const int e_g = tid >> 1;
    const int qb  = tid & 1;
    const int dflag = s_dst[e_g];
    const int doff  = s_doff[e_g];
    const int soff  = s_soff[e_g];
    const float dist = s_dist[e_g];

    const int tx = tid & 15;
    const int ty = tid >> 4;
    const int e0 = ty * 8;

    // staging coords for vectorized We2 chunk copy
    const int stg_k  = tid >> 3;          // 0..31
    const int stg_j0 = (tid & 7) * 8;     // 0..56

    u64t macc[4][4];
    #pragma unroll
    for (int p = 0; p < 4; p++)
        #pragma unroll
        for (int j = 0; j < 4; j++) macc[p][j] = 0ull;

    float4 P1[4], P2[4];
    #pragma unroll
    for (int it = 0; it < 4; it++) {
        int c = 4 * (qb + 2 * it);
        P1[it] = *(const float4*)&g_p[(size_t)(doff + c)];
        P2[it] = *(const float4*)&g_p[(size_t)(soff + c)];
    }
    float4 T1 = make_float4(0.f, 0.f, 0.f, 0.f);
    float4 T2 = make_float4(0.f, 0.f, 0.f, 0.f);

    for (int chunk = 0; chunk < 16; chunk++) {
        int c0 = chunk * 32;

        #pragma unroll
        for (int it = 0; it < 4; it++) {
            int q = qb + 2 * it;
            float4 wd4 = *(const float4*)&s_wd[4 * q];
            float4 bb4 = *(const float4*)&s_bb[4 * q];
            float h0 = silu_f(fmaf(dist, wd4.x, P1[it].x + P2[it].x + bb4.x));
            float h1 = silu_f(fmaf(dist, wd4.y, P1[it].y + P2[it].y + bb4.y));
            float h2 = silu_f(fmaf(dist, wd4.z, P1[it].z + P2[it].z + bb4.z));
            float h3 = silu_f(fmaf(dist, wd4.w, P1[it].w + P2[it].w + bb4.w));
            if (dflag < 0) { h0 = 0.f; h1 = 0.f; h2 = 0.f; h3 = 0.f; }
            s_h[(4 * q + 0) * 132 + e_g] = h0;
            s_h[(4 * q + 1) * 132 + e_g] = h1;
            s_h[(4 * q + 2) * 132 + e_g] = h2;
            s_h[(4 * q + 3) * 132 + e_g] = h3;
        }
        // vectorized We2 chunk staging: 2x LDG.128 + 2x STS.128 per thread
        {
            const float* src = &We2[(c0 + stg_k) * 64 + stg_j0];
            float4 v0 = *(const float4*)src;
            float4 v1 = *(const float4*)(src + 4);
            *(float4*)&s_w2[stg_k * 64 + stg_j0]     = v0;
            *(float4*)&s_w2[stg_k * 64 + stg_j0 + 4] = v1;
        }
        __syncthreads();

        if (chunk < 15) {
            int c0n = c0 + 32;
            #pragma unroll
            for (int it = 0; it < 4; it++) {
                int c = c0n + 4 * (qb + 2 * it);
                P1[it] = *(const float4*)&g_p[(size_t)(doff + c)];
                P2[it] = *(const float4*)&g_p[(size_t)(soff + c)];
            }
            if (tid < 32) {
                int col = c0n + tid;
                s_bb[tid] = be1[col];
                s_wd[tid] = We1[256 * 514 + col];
            }
        } else if (qb == 0) {
            T1 = *(const float4*)&g_p[(size_t)(doff + 512)];
            T2 = *(const float4*)&g_p[(size_t)(soff + 512)];
        }

        #pragma unroll 4
        for (int c = 0; c < 32; c++) {
            ulonglong2 A0 = *(const ulonglong2*)&s_h[c * 132 + e0];
            ulonglong2 A1 = *(const ulonglong2*)&s_h[c * 132 + e0 + 4];
            float4 bv = *(const float4*)&s_w2[c * 64 + (tx << 2)];
            u64t B0 = pack2s(bv.x), B1 = pack2s(bv.y), B2 = pack2s(bv.z), B3 = pack2s(bv.w);
            ffma2(macc[0][0], A0.x, B0); ffma2(macc[0][1], A0.x, B1);
            ffma2(macc[0][2], A0.x, B2); ffma2(macc[0][3], A0.x, B3);
            ffma2(macc[1][0], A0.y, B0); ffma2(macc[1][1], A0.y, B1);
            ffma2(macc[1][2], A0.y, B2); ffma2(macc[1][3], A0.y, B3);
            ffma2(macc[2][0], A1.x, B0); ffma2(macc[2][1], A1.x, B1);
            ffma2(macc[2][2], A1.x, B2); ffma2(macc[2][3], A1.x, B3);
            ffma2(macc[3][0], A1.y, B0); ffma2(macc[3][1], A1.y, B1);
            ffma2(macc[3][2], A1.y, B2); ffma2(macc[3][3], A1.y, B3);
        }
        __syncthreads();
    }

    // tail: cols 512, 513
    if (tid < 128)
        s_w2[tid] = We2[(512 + (tid >> 6)) * 64 + (tid & 63)];
    if (qb == 0) {
        float wd0 = We1[256 * 514 + 512], wd1 = We1[256 * 514 + 513];
        float b0 = be1[512], b1 = be1[513];
        float h0 = silu_f(fmaf(dist, wd0, T1.x + T2.x + b0));
        float h1 = silu_f(fmaf(dist, wd1, T1.y + T2.y + b1));
        if (dflag < 0) { h0 = 0.f; h1 = 0.f; }
        s_h[e_g]       = h0;
        s_h[132 + e_g] = h1;
    }
    __syncthreads();
    #pragma unroll
    for (int c = 0; c < 2; c++) {
        ulonglong2 A0 = *(const ulonglong2*)&s_h[c * 132 + e0];
        ulonglong2 A1 = *(const ulonglong2*)&s_h[c * 132 + e0 + 4];
        float4 bv = *(const float4*)&s_w2[c * 64 + (tx << 2)];
        u64t B0 = pack2s(bv.x), B1 = pack2s(bv.y), B2 = pack2s(bv.z), B3 = pack2s(bv.w);
        ffma2(macc[0][0], A0.x, B0); ffma2(macc[0][1], A0.x, B1);
        ffma2(macc[0][2], A0.x, B2); ffma2(macc[0][3], A0.x, B3);
        ffma2(macc[1][0], A0.y, B0); ffma2(macc[1][1], A0.y, B1);
        ffma2(macc[1][2], A0.y, B2); ffma2(macc[1][3], A0.y, B3);
        ffma2(macc[2][0], A1.x, B0); ffma2(macc[2][1], A1.x, B1);
        ffma2(macc[2][2], A1.x, B2); ffma2(macc[2][3], A1.x, B3);
        ffma2(macc[3][0], A1.y, B0); ffma2(macc[3][1], A1.y, B1);
        ffma2(macc[3][2], A1.y, B2); ffma2(macc[3][3], A1.y, B3);
    }
    __syncthreads();

    // m_ij = silu(m + b_e2); store + atomic scatter
    float mval[8][4];
    #pragma unroll
    for (int j = 0; j < 4; j++) {
        float b = be2[tx * 4 + j];
        #pragma unroll
        for (int p = 0; p < 4; p++) {
            float2 v = unpack2(macc[p][j]);
            mval[2 * p][j]     = silu_f(v.x + b);
            mval[2 * p + 1][j] = silu_f(v.y + b);
        }
    }
    #pragma unroll
    for (int j = 0; j < 4; j++)
        #pragma unroll
        for (int i = 0; i < 8; i++)
            s_m[(tx * 4 + j) * 132 + e0 + i] = mval[i][j];
    #pragma unroll
    for (int i = 0; i < 8; i++) {
        int d = s_dst[e0 + i];
        if (d >= 0) {
            #pragma unroll
            for (int j = 0; j < 4; j++)
                atomicAdd(&g_m[d * 64 + tx * 4 + j], mval[i][j]);
        }
    }
    __syncthreads();

    // GEMM3 (64->256) + silu + dot W_c2 (FFMA2)
    float cw[8];
    #pragma unroll
    for (int i = 0; i < 8; i++) cw[i] = 0.0f;

    for (int c0 = 0; c0 < 256; c0 += 32) {
        // vectorized Wc1 chunk staging: [64][32] = 512 float4, 2 per thread
        #pragma unroll
        for (int i = 0; i < 2; i++) {
            int q = tid + i * 256;
            int row = q >> 3;
            int c4  = (q & 7) * 4;
            *(float4*)&s_wc[row * 32 + c4] = *(const float4*)&Wc1[row * 256 + c0 + c4];
        }
        __syncthreads();

        u64t acc[4][2];
        #pragma unroll
        for (int p = 0; p < 4; p++) { acc[p][0] = 0ull; acc[p][1] = 0ull; }

        for (int k = 0; k < 64; k += 4) {
            #pragma unroll
            for (int kk = 0; kk < 4; kk++) {
                ulonglong2 A0 = *(const ulonglong2*)&s_m[(k + kk) * 132 + e0];
                ulonglong2 A1 = *(const ulonglong2*)&s_m[(k + kk) * 132 + e0 + 4];
                float2 bv = *(const float2*)&s_wc[(k + kk) * 32 + (tx << 1)];
                u64t B0 = pack2s(bv.x), B1 = pack2s(bv.y);
                ffma2(acc[0][0], A0.x, B0); ffma2(acc[0][1], A0.x, B1);
                ffma2(acc[1][0], A0.y, B0); ffma2(acc[1][1], A0.y, B1);
                ffma2(acc[2][0], A1.x, B0); ffma2(acc[2][1], A1.x, B1);
                ffma2(acc[3][0], A1.y, B0); ffma2(acc[3][1], A1.y, B1);
            }
        }
        float bb0 = bc1[c0 + tx * 2], bb1 = bc1[c0 + tx * 2 + 1];
        float w20 = Wc2[c0 + tx * 2], w21 = Wc2[c0 + tx * 2 + 1];
        #pragma unroll
        for (int p = 0; p < 4; p++) {
            float2 v0 = unpack2(acc[p][0]);
            float2 v1 = unpack2(acc[p][1]);
            cw[2 * p]     += silu_f(v0.x + bb0) * w20 + silu_f(v1.x + bb1) * w21;
            cw[2 * p + 1] += silu_f(v0.y + bb0) * w20 + silu_f(v1.y + bb1) * w21;
        }
        __syncthreads();
    }

    #pragma unroll
    for (int off = 8; off >= 1; off >>= 1)
        #pragma unroll
        for (int i = 0; i < 8; i++)
            cw[i] += __shfl_xor_sync(0xffffffffu, cw[i], off);

    if (tx == 0) {
        float bc2v = bc2[0];
        #pragma unroll
        for (int i = 0; i < 8; i++) {
            int d = s_dst[e0 + i];
            if (d >= 0) {
                atomicAdd(&g_w[d], cw[i] + bc2v);
                atomicAdd(&g_r[d * 3 + 0], s_rel[(e0 + i) * 3 + 0]);
                atomicAdd(&g_r[d * 3 + 1], s_rel[(e0 + i) * 3 + 1]);
                atomicAdd(&g_r[d * 3 + 2], s_rel[(e0 + i) * 3 + 2]);
            }
        }
    }
}

// ---------------------------------------------------------------------------
// Node kernel (R9 64-node version, staging vectorized)
// Shared: s_nin [64][196] (12544) | s_w1 [192][32] (6144)
//         | s_h1 [32][68] (2176) | s_w2 [32][128] (4096) = 24960 fl = 99840 B
// ---------------------------------------------------------------------------
#define NODE_SMEM_BYTES 99840

__global__ __launch_bounds__(256)
void node_kernel(const float* __restrict__ x,
                 const float* __restrict__ Wn1, const float* __restrict__ bn1,
                 const float* __restrict__ Wn2, const float* __restrict__ bn2,
                 float* __restrict__ out)
{
    extern __shared__ float sm[];
    float* s_nin = sm;              // [64][196]
    float* s_w1  = sm + 12544;      // [192][32]
    float* s_h1  = sm + 18688;      // [32][68]
    float* s_w2  = sm + 20864;      // [32][128]

    const int tid  = threadIdx.x;
    const int lane = tid & 31;
    const int wrp  = tid >> 5;
    const int b0   = blockIdx.x * 64;

    for (int i = wrp; i < 64; i += 8) {
        int g = b0 + i;
        if (g < NN) {
            const float* xr = x + (size_t)g * 131;
            #pragma unroll
            for (int c = lane; c < 128; c += 32) s_nin[i * 196 + c] = xr[c];
            if (lane < 16)
                *(float4*)&s_nin[i * 196 + 128 + lane * 4] =
                    *(const float4*)&g_m[(size_t)g * 64 + lane * 4];
            if (lane < 4) s_nin[i * 196 + 192 + lane] = 0.0f;
            if (lane < 3)
                out[(size_t)g * 131 + 128 + lane] = xr[128 + lane] + g_w[g] * g_r[g * 3 + lane];
        } else {
            for (int c = lane; c < 196; c += 32) s_nin[i * 196 + c] = 0.0f;
        }
    }
    __syncthreads();

    const int tx = tid & 15;
    const int ty = tid >> 4;

    u64t pacc[4][4];
    #pragma unroll
    for (int i = 0; i < 4; i++)
        #pragma unroll
        for (int q = 0; q < 4; q++) pacc[i][q] = 0ull;

    for (int c0 = 0; c0 < 256; c0 += 32) {
        // s_w1 [192][32] = 1536 float4; 6 per thread
        #pragma unroll
        for (int i = 0; i < 6; i++) {
            int q = tid + i * 256;
            int row = q >> 3;
            int c4  = (q & 7) * 4;
            *(float4*)&s_w1[row * 32 + c4] = *(const float4*)&Wn1[row * 256 + c0 + c4];
        }
        __syncthreads();

        u64t acc1p[4];
        #pragma unroll
        for (int i = 0; i < 4; i++) acc1p[i] = 0ull;

        for (int k = 0; k < 192; k += 4) {
            float4 a[4];
            #pragma unroll
            for (int i = 0; i < 4; i++)
                a[i] = *(const float4*)&s_nin[(ty * 4 + i) * 196 + k];
            #pragma unroll
            for (int kk = 0; kk < 4; kk++) {
                u64t bp = *(const u64t*)&s_w1[(k + kk) * 32 + (tx << 1)];
                #pragma unroll
                for (int i = 0; i < 4; i++) {
                    float av = (kk == 0) ? a[i].x : (kk == 1) ? a[i].y : (kk == 2) ? a[i].z : a[i].w;
                    ffma2(acc1p[i], pack2s(av), bp);
                }
            }
        }
        __syncthreads();

        {
            float bjx = bn1[c0 + tx * 2];
            float bjy = bn1[c0 + tx * 2 + 1];
            #pragma unroll
            for (int i = 0; i < 4; i++) {
                float2 v = unpack2(acc1p[i]);
                s_h1[(tx * 2)     * 68 + ty * 4 + i] = silu_f(v.x + bjx);
                s_h1[(tx * 2 + 1) * 68 + ty * 4 + i] = silu_f(v.y + bjy);
            }
        }
        // s_w2 [32][128] = 1024 float4; 4 per thread
        #pragma unroll
        for (int i = 0; i < 4; i++) {
            int q = tid + i * 256;
            int row = q >> 5;
            int c4  = (q & 31) * 4;
            *(float4*)&s_w2[row * 128 + c4] = *(const float4*)&Wn2[(c0 + row) * 128 + c4];
        }
        __syncthreads();

        #pragma unroll 4
        for (int c = 0; c < 32; c++) {
            float4 a = *(const float4*)&s_h1[c * 68 + ty * 4];
            ulonglong2 B0 = *(const ulonglong2*)&s_w2[c * 128 + tx * 8];
            ulonglong2 B1 = *(const ulonglong2*)&s_w2[c * 128 + tx * 8 + 4];
            #pragma unroll
            for (int i = 0; i < 4; i++) {
                float av = (i == 0) ? a.x : (i == 1) ? a.y : (i == 2) ? a.z : a.w;
                u64t Ap = pack2s(av);
                ffma2(pacc[i][0], Ap, B0.x);
                ffma2(pacc[i][1], Ap, B0.y);
                ffma2(pacc[i][2], Ap, B1.x);
                ffma2(pacc[i][3], Ap, B1.y);
            }
        }
        __syncthreads();
    }

    #pragma unroll
    for (int i = 0; i < 4; i++) {
        int g = b0 + ty * 4 + i;
        if (g < NN) {
            #pragma unroll
            for (int q = 0; q < 4; q++) {
                float2 v = unpack2(pacc[i][q]);
                int col = tx * 8 + 2 * q;
                out[(size_t)g * 131 + col] =
                    v.x + bn2[col] + s_nin[(ty * 4 + i) * 196 + col];
                out[(size_t)g * 131 + col + 1] =
                    v.y + bn2[col + 1] + s_nin[(ty * 4 + i) * 196 + col + 1];
            }
        }
    }
}

// ---------------------------------------------------------------------------
extern "C" void kernel_launch(void* const* d_in, const int* in_sizes, int n_in,
                              void* d_out, int out_size)
{
    const float* x   = (const float*)d_in[0];
    const void*  ei  = d_in[1];
    const float* We1 = (const float*)d_in[2];
    const float* be1 = (const float*)d_in[3];
    const float* We2 = (const float*)d_in[4];
    const float* be2 = (const float*)d_in[5];
    const float* Wc1 = (const float*)d_in[6];
    const float* bc1 = (const float*)d_in[7];
    const float* Wc2 = (const float*)d_in[8];
    const float* bc2 = (const float*)d_in[9];
    const float* Wn1 = (const float*)d_in[10];
    const float* bn1 = (const float*)d_in[11];
    const float* Wn2 = (const float*)d_in[12];
    const float* bn2 = (const float*)d_in[13];
    float* out = (float*)d_out;

    cudaFuncSetAttribute(pre_kernel,  cudaFuncAttributeMaxDynamicSharedMemorySize, PRE_SMEM_BYTES);
    cudaFuncSetAttribute(edge_kernel, cudaFuncAttributeMaxDynamicSharedMemorySize, EDGE_SMEM_BYTES);
    cudaFuncSetAttribute(node_kernel, cudaFuncAttributeMaxDynamicSharedMemorySize, NODE_SMEM_BYTES);

    zero_kernel<<<1024, 256>>>((const int*)ei);
    pre_kernel<<<(NN + 127) / 128, 256, PRE_SMEM_BYTES>>>(x, We1);
    edge_kernel<<<(EE + 127) / 128, 256, EDGE_SMEM_BYTES>>>(
        x, ei, We1, be1, We2, be2, Wc1, bc1, Wc2, bc2);
    node_kernel<<<(NN + 63) / 64, 256, NODE_SMEM_BYTES>>>(
        x, Wn1, bn1, Wn2, bn2, out);
}